// round 4
// baseline (speedup 1.0000x reference)
#include <cuda_runtime.h>
#include <cstdint>
#include <cstddef>

// ---------------------------------------------------------------------------
// Problem constants
// ---------------------------------------------------------------------------
#define B_TOT   8192
#define NB      4            // batch elems per block in kernel 1
#define KFEAT   1600         // 64 channels * 25 positions
#define OUTC    5

typedef unsigned long long ull;

// Staged activations (relu'd concat features), scratch: __device__ global (no allocs)
__device__ float g_Y[(size_t)B_TOT * KFEAT];

// ---------------------------------------------------------------------------
// f32x2 helpers (FFMA2 — ptxas never auto-fuses; PTX-only on sm_100+/103a)
// ---------------------------------------------------------------------------
__device__ __forceinline__ ull pk2(float lo, float hi) {
    ull r; asm("mov.b64 %0, {%1,%2};" : "=l"(r) : "f"(lo), "f"(hi)); return r;
}
__device__ __forceinline__ ull ffma2(ull a, ull b, ull c) {
    ull d; asm("fma.rn.f32x2 %0, %1, %2, %3;" : "=l"(d) : "l"(a), "l"(b), "l"(c)); return d;
}
__device__ __forceinline__ void upk2(ull v, float& lo, float& hi) {
    asm("mov.b64 {%0,%1}, %2;" : "=f"(lo), "=f"(hi) : "l"(v));
}

// ---------------------------------------------------------------------------
// Kernel 1: fused conv2x2 (conv_out + qkv) + attention + 1x1 conv + relu
//   grid = 2048 blocks (4 batch elems each), 256 threads, dyn smem 85120 B
//
// smem float offsets
// ---------------------------------------------------------------------------
#define K1_WT    0                     // 64*128  transposed combined conv+qkv weights
#define K1_BIAS  (K1_WT + 8192)        // 128
#define K1_AW    (K1_BIAS + 128)       // 1024    attn 1x1 weights
#define K1_AB    (K1_AW + 1024)        // 32
#define K1_X     (K1_AB + 32)          // NB*576  (16B-aligned: 9376 floats)
#define K1_QKV   (K1_X + 2304)         // NB*96*25
#define K1_TOT   (K1_QKV + 9600)       // 21280 floats = 85120 B

extern "C" __global__ void __launch_bounds__(256, 2)
k1_conv_attn(const float* __restrict__ x,
             const float* __restrict__ conv_w, const float* __restrict__ conv_b,
             const float* __restrict__ qkv_w,  const float* __restrict__ qkv_b,
             const float* __restrict__ attn_w, const float* __restrict__ attn_b)
{
    extern __shared__ float sm[];
    float* wT   = sm + K1_WT;
    float* bias = sm + K1_BIAS;
    float* aw   = sm + K1_AW;
    float* ab   = sm + K1_AB;
    float* xs   = sm + K1_X;
    float* qkv  = sm + K1_QKV;

    const int tid = threadIdx.x;
    const int b0  = blockIdx.x * NB;

    // ---- cooperative loads ----
    // Combined weight, transposed: wT[k][oc], k = ic*4 + di*2 + dj, oc in [0,128)
    for (int idx = tid; idx < 8192; idx += 256) {
        int k = idx >> 7, oc = idx & 127;
        wT[idx] = (oc < 32) ? conv_w[oc * 64 + k] : qkv_w[(oc - 32) * 64 + k];
    }
    if (tid < 128) bias[tid] = (tid < 32) ? conv_b[tid] : qkv_b[tid - 32];
    for (int idx = tid; idx < 1024; idx += 256) aw[idx] = attn_w[idx];
    if (tid < 32) ab[tid] = attn_b[tid];
    {
        const float4* src = reinterpret_cast<const float4*>(x + (size_t)b0 * 576);
        float4* dst = reinterpret_cast<float4*>(xs);
        for (int idx = tid; idx < 576; idx += 256) dst[idx] = src[idx];
    }
    __syncthreads();

    // ---- Phase A: 2x2 VALID conv, 128 out channels x (NB*25) positions ----
    // One task = 8 consecutive output channels at one (batch,pos).
    // Warp: lanes 0-15 / 16-31 share a (batch,pos) -> x reads broadcast;
    // weight reads are LDS.128 pairs, accumulation in f32x2.
    for (int t = tid; t < NB * 25 * 16; t += 256) {
        int g   = t & 15;                 // channel octet
        int pr  = t >> 4;                 // (bb, pos)
        int bb  = pr / 25, pos = pr - bb * 25;
        int i   = pos / 5,  j  = pos - i * 5;
        int oc0 = g << 3;
        const float* xb = xs + bb * 576 + i * 6 + j;

        ull a0 = pk2(bias[oc0 + 0], bias[oc0 + 1]);
        ull a1 = pk2(bias[oc0 + 2], bias[oc0 + 3]);
        ull a2 = pk2(bias[oc0 + 4], bias[oc0 + 5]);
        ull a3 = pk2(bias[oc0 + 6], bias[oc0 + 7]);

        #pragma unroll
        for (int ic = 0; ic < 16; ++ic) {
            const float* xc = xb + ic * 36;
            float xv0 = xc[0], xv1 = xc[1], xv2 = xc[6], xv3 = xc[7];
            const float* wr = wT + (ic * 4) * 128 + oc0;
            #pragma unroll
            for (int kk = 0; kk < 4; ++kk) {
                float xv = (kk == 0) ? xv0 : (kk == 1) ? xv1 : (kk == 2) ? xv2 : xv3;
                ull xx = pk2(xv, xv);
                const ulonglong2* wp = reinterpret_cast<const ulonglong2*>(wr + kk * 128);
                ulonglong2 wA = wp[0];      // oc0..oc0+3
                ulonglong2 wB = wp[1];      // oc0+4..oc0+7
                a0 = ffma2(xx, wA.x, a0);
                a1 = ffma2(xx, wA.y, a1);
                a2 = ffma2(xx, wB.x, a2);
                a3 = ffma2(xx, wB.y, a3);
            }
        }
        float r[8];
        upk2(a0, r[0], r[1]); upk2(a1, r[2], r[3]);
        upk2(a2, r[4], r[5]); upk2(a3, r[6], r[7]);

        if (oc0 < 32) {
            // conv_out path: relu happens after concat -> apply now, store to Y
            float* dst = g_Y + (size_t)(b0 + bb) * KFEAT + oc0 * 25 + pos;
            #pragma unroll
            for (int l = 0; l < 8; ++l) dst[l * 25] = fmaxf(r[l], 0.f);
        } else {
            // qkv path (dkh^-0.5 == 1, no scaling): stash in smem
            float* dst = qkv + (bb * 96 + (oc0 - 32)) * 25 + pos;
            #pragma unroll
            for (int l = 0; l < 8; ++l) dst[l * 25] = r[l];
        }
    }
    __syncthreads();

    // ---- Phase B: attention. dkh=1 => logits[i][j] = q_i * k_j ----
    // unit u = (bb, head n); lane = query index i. Each thread reads only its
    // own q element, then overwrites that slot with the attention output
    // (channels 0..31 of qkv become the attn map) — safe: 1 owner per element.
    {
        const int lane = tid & 31;
        const int w    = tid >> 5;
        #pragma unroll 1
        for (int it = 0; it < 16; ++it) {
            int u = w + it * 8;                    // 0..127
            if (lane < 25) {
                int bb = u >> 5, n = u & 31;
                const float* qrow = qkv + (bb * 96 + n) * 25;
                const float* krow = qrow + 32 * 25;
                const float* vrow = qrow + 64 * 25;
                float qi = qrow[lane];
                float p[25]; float m = -1e30f;
                #pragma unroll
                for (int jj = 0; jj < 25; ++jj) { p[jj] = qi * krow[jj]; m = fmaxf(m, p[jj]); }
                float s = 0.f, a = 0.f;
                #pragma unroll
                for (int jj = 0; jj < 25; ++jj) {
                    float e = __expf(p[jj] - m);
                    s += e;
                    a = fmaf(e, vrow[jj], a);
                }
                qkv[(bb * 96 + n) * 25 + lane] = a / s;
            }
        }
    }
    __syncthreads();

    // ---- Phase C: 1x1 conv over attn channels, relu, store to Y[32..63] ----
    {
        const int lane = tid & 31;
        const int w    = tid >> 5;
        #pragma unroll 1
        for (int it = 0; it < 16; ++it) {
            int u = w + it * 8;
            if (lane < 25) {
                int bb = u >> 5, oc = u & 31;
                float acc = ab[oc];
                const float* arow = qkv + bb * 96 * 25;   // channels 0..31 = attn
                #pragma unroll
                for (int ic = 0; ic < 32; ++ic)
                    acc = fmaf(aw[oc * 32 + ic], arow[ic * 25 + lane], acc);
                g_Y[(size_t)(b0 + bb) * KFEAT + (32 + oc) * 25 + lane] = fmaxf(acc, 0.f);
            }
        }
    }
}

// ---------------------------------------------------------------------------
// Kernel 2: fc1 (64x128x1600 SGEMM per block, f32x2) + fc2 + fc3 fused
//   grid = 128 blocks (64 rows each), 256 threads, dyn smem 97056 B
// ---------------------------------------------------------------------------
#define K2_AS   0                      // 64*17
#define K2_BS   (K2_AS + 1088)         // 16*128  (offset 4352 B -> 16B aligned)
#define K2_B1   (K2_BS + 2048)         // 128
#define K2_W2   (K2_B1 + 128)          // 64*128
#define K2_B2   (K2_W2 + 8192)         // 64
#define K2_W3   (K2_B2 + 64)           // 5*64
#define K2_B3   (K2_W3 + 320)          // 8 (pad)
#define K2_H1   (K2_B3 + 8)            // 64*129
#define K2_H2   (K2_H1 + 8256)         // 64*65
#define K2_TOT  (K2_H2 + 4160)         // 24264 floats = 97056 B

extern "C" __global__ void __launch_bounds__(256, 1)
k2_mlp(const float* __restrict__ w1, const float* __restrict__ b1,
       const float* __restrict__ w2, const float* __restrict__ b2,
       const float* __restrict__ w3, const float* __restrict__ b3,
       float* __restrict__ out)
{
    extern __shared__ float sm[];
    float* As  = sm + K2_AS;
    float* Bs  = sm + K2_BS;
    float* b1s = sm + K2_B1;
    float* w2s = sm + K2_W2;
    float* b2s = sm + K2_B2;
    float* w3s = sm + K2_W3;
    float* b3s = sm + K2_B3;
    float* H1s = sm + K2_H1;
    float* H2s = sm + K2_H2;

    const int tid = threadIdx.x;
    const int rowBase = blockIdx.x * 64;

    // ---- preload small weights ----
    for (int idx = tid; idx < 8192; idx += 256) w2s[idx] = w2[idx];
    for (int idx = tid; idx < 320;  idx += 256) w3s[idx] = w3[idx];
    if (tid < 128) b1s[tid] = b1[tid];
    if (tid < 64)  b2s[tid] = b2[tid];
    if (tid < 8)   b3s[tid] = (tid < 5) ? b3[tid] : 0.f;

    // ---- fc1 GEMM: C[64x128] = Y[64x1600] @ w1^T, 4x8 microtile, f32x2 ----
    const int tx = tid & 15;           // column group (8 cols)
    const int ty = tid >> 4;           // row group   (4 rows)
    const int r0 = ty * 4;
    const int c0 = tx * 8;

    ull acc[4][4];
    #pragma unroll
    for (int i = 0; i < 4; ++i)
        #pragma unroll
        for (int p = 0; p < 4; ++p) acc[i][p] = 0ull;

    const int rowA = tid >> 2, kqA  = (tid & 3) * 4;
    const int nB0  = tid >> 2, kqB0 = (tid & 3) * 4;
    const int nB1  = (tid + 256) >> 2, kqB1 = ((tid + 256) & 3) * 4;

    const float* Yrow = g_Y + (size_t)(rowBase + rowA) * KFEAT;
    const float* w1r0 = w1 + (size_t)nB0 * KFEAT;
    const float* w1r1 = w1 + (size_t)nB1 * KFEAT;

    float4 aR, bR0, bR1;
    aR  = *reinterpret_cast<const float4*>(Yrow + kqA);
    bR0 = *reinterpret_cast<const float4*>(w1r0 + kqB0);
    bR1 = *reinterpret_cast<const float4*>(w1r1 + kqB1);

    #pragma unroll 1
    for (int it = 0; it < 100; ++it) {
        __syncthreads();
        // stage current tile into smem
        As[rowA * 17 + kqA + 0] = aR.x;
        As[rowA * 17 + kqA + 1] = aR.y;
        As[rowA * 17 + kqA + 2] = aR.z;
        As[rowA * 17 + kqA + 3] = aR.w;
        Bs[(kqB0 + 0) * 128 + nB0] = bR0.x;
        Bs[(kqB0 + 1) * 128 + nB0] = bR0.y;
        Bs[(kqB0 + 2) * 128 + nB0] = bR0.z;
        Bs[(kqB0 + 3) * 128 + nB0] = bR0.w;
        Bs[(kqB1 + 0) * 128 + nB1] = bR1.x;
        Bs[(kqB1 + 1) * 128 + nB1] = bR1.y;
        Bs[(kqB1 + 2) * 128 + nB1] = bR1.z;
        Bs[(kqB1 + 3) * 128 + nB1] = bR1.w;
        __syncthreads();

        // register-prefetch next K chunk (latency hidden under compute)
        if (it < 99) {
            int k0 = (it + 1) * 16;
            aR  = *reinterpret_cast<const float4*>(Yrow + k0 + kqA);
            bR0 = *reinterpret_cast<const float4*>(w1r0 + k0 + kqB0);
            bR1 = *reinterpret_cast<const float4*>(w1r1 + k0 + kqB1);
        }

        #pragma unroll
        for (int kk = 0; kk < 16; ++kk) {
            const ulonglong2* bp = reinterpret_cast<const ulonglong2*>(Bs + kk * 128 + c0);
            ulonglong2 bA = bp[0], bB = bp[1];
            #pragma unroll
            for (int i = 0; i < 4; ++i) {
                float av = As[(r0 + i) * 17 + kk];
                ull aa = pk2(av, av);
                acc[i][0] = ffma2(aa, bA.x, acc[i][0]);
                acc[i][1] = ffma2(aa, bA.y, acc[i][1]);
                acc[i][2] = ffma2(aa, bB.x, acc[i][2]);
                acc[i][3] = ffma2(aa, bB.y, acc[i][3]);
            }
        }
    }

    // ---- epilogue: +b1, relu -> H1s ----
    #pragma unroll
    for (int i = 0; i < 4; ++i)
        #pragma unroll
        for (int p = 0; p < 4; ++p) {
            float lo, hi; upk2(acc[i][p], lo, hi);
            H1s[(r0 + i) * 129 + c0 + 2 * p]     = fmaxf(lo + b1s[c0 + 2 * p],     0.f);
            H1s[(r0 + i) * 129 + c0 + 2 * p + 1] = fmaxf(hi + b1s[c0 + 2 * p + 1], 0.f);
        }
    __syncthreads();

    // ---- fc2: 64 rows x 64 outs, K=128, relu ----
    for (int t = tid; t < 4096; t += 256) {
        int o = t >> 6, row = t & 63;
        float a = b2s[o];
        #pragma unroll
        for (int k = 0; k < 128; ++k)
            a = fmaf(H1s[row * 129 + k], w2s[o * 128 + k], a);
        H2s[row * 65 + o] = fmaxf(a, 0.f);
    }
    __syncthreads();

    // ---- fc3: 64 rows x 5 outs, K=64 ----
    for (int t = tid; t < 320; t += 256) {
        int o = t / 64, row = t - o * 64;
        float a = b3s[o];
        #pragma unroll
        for (int k = 0; k < 64; ++k)
            a = fmaf(H2s[row * 65 + k], w3s[o * 64 + k], a);
        out[(size_t)(rowBase + row) * OUTC + o] = a;
    }
}

// ---------------------------------------------------------------------------
// Launch (graph-capturable: kernel launches only, default stream)
// ---------------------------------------------------------------------------
extern "C" void kernel_launch(void* const* d_in, const int* in_sizes, int n_in,
                              void* d_out, int out_size)
{
    const float* x      = (const float*)d_in[0];
    const float* conv_w = (const float*)d_in[1];
    const float* conv_b = (const float*)d_in[2];
    const float* qkv_w  = (const float*)d_in[3];
    const float* qkv_b  = (const float*)d_in[4];
    const float* attn_w = (const float*)d_in[5];
    const float* attn_b = (const float*)d_in[6];
    const float* w1     = (const float*)d_in[7];
    const float* b1     = (const float*)d_in[8];
    const float* w2     = (const float*)d_in[9];
    const float* b2     = (const float*)d_in[10];
    const float* w3     = (const float*)d_in[11];
    const float* b3     = (const float*)d_in[12];
    float* out = (float*)d_out;

    const int SM1 = K1_TOT * (int)sizeof(float);   // 85120 B
    const int SM2 = K2_TOT * (int)sizeof(float);   // 97056 B
    cudaFuncSetAttribute(k1_conv_attn, cudaFuncAttributeMaxDynamicSharedMemorySize, SM1);
    cudaFuncSetAttribute(k2_mlp,       cudaFuncAttributeMaxDynamicSharedMemorySize, SM2);

    k1_conv_attn<<<B_TOT / NB, 256, SM1>>>(x, conv_w, conv_b, qkv_w, qkv_b, attn_w, attn_b);
    k2_mlp<<<B_TOT / 64, 256, SM2>>>(w1, b1, w2, b2, w3, b3, out);
}

// round 5
// speedup vs baseline: 1.7320x; 1.7320x over previous
#include <cuda_runtime.h>
#include <cstdint>
#include <cstddef>

// ---------------------------------------------------------------------------
// Problem constants
// ---------------------------------------------------------------------------
#define B_TOT   8192
#define NB      4            // batch elems per block in kernel 1
#define KFEAT   1600         // 64 channels * 25 positions
#define OUTC    5

typedef unsigned long long ull;

// Scratch (__device__ globals — no allocs allowed)
__device__ float g_Y[(size_t)B_TOT * KFEAT];   // staged relu'd features
__device__ float g_wT[64 * 128];               // transposed combined conv+qkv weights
__device__ float g_bias[128];                  // combined conv+qkv bias
__device__ float g_awT[32 * 32];               // transposed attn 1x1 weights

// ---------------------------------------------------------------------------
// f32x2 helpers (FFMA2 — PTX-only; ptxas never auto-fuses)
// ---------------------------------------------------------------------------
__device__ __forceinline__ ull pk2(float lo, float hi) {
    ull r; asm("mov.b64 %0, {%1,%2};" : "=l"(r) : "f"(lo), "f"(hi)); return r;
}
__device__ __forceinline__ ull ffma2(ull a, ull b, ull c) {
    ull d; asm("fma.rn.f32x2 %0, %1, %2, %3;" : "=l"(d) : "l"(a), "l"(b), "l"(c)); return d;
}
__device__ __forceinline__ void upk2(ull v, float& lo, float& hi) {
    asm("mov.b64 {%0,%1}, %2;" : "=f"(lo), "=f"(hi) : "l"(v));
}
__device__ __forceinline__ float ex2f(float x) {
    float y; asm("ex2.approx.f32 %0, %1;" : "=f"(y) : "f"(x)); return y;
}

// ---------------------------------------------------------------------------
// Kernel 0: one-time weight repack (transpose to coalesced-load layouts)
// ---------------------------------------------------------------------------
extern "C" __global__ void k0_prep(const float* __restrict__ conv_w,
                                   const float* __restrict__ conv_b,
                                   const float* __restrict__ qkv_w,
                                   const float* __restrict__ qkv_b,
                                   const float* __restrict__ attn_w)
{
    int t = blockIdx.x * blockDim.x + threadIdx.x;
    for (int idx = t; idx < 8192; idx += 1024) {
        int k = idx >> 7, oc = idx & 127;
        g_wT[idx] = (oc < 32) ? conv_w[oc * 64 + k] : qkv_w[(oc - 32) * 64 + k];
    }
    for (int idx = t; idx < 1024; idx += 1024) {
        int ic = idx >> 5, oc = idx & 31;
        g_awT[idx] = attn_w[oc * 32 + ic];
    }
    if (t < 128) g_bias[t] = (t < 32) ? conv_b[t] : qkv_b[t - 32];
}

// ---------------------------------------------------------------------------
// Kernel 1: fused conv2x2 (conv_out + qkv) + attention + 1x1 conv + relu
//   grid = 2048 blocks (4 batch elems each), 320 threads, dyn smem 85120 B
//
// smem float offsets
// ---------------------------------------------------------------------------
#define K1_WT    0                     // 64*128
#define K1_BIAS  8192                  // 128
#define K1_AWT   8320                  // 1024
#define K1_AB    9344                  // 32
#define K1_XS    9376                  // NB*576
#define K1_QKV   11680                 // NB*96*25
#define K1_TOT   21280                 // 85120 B

extern "C" __global__ void __launch_bounds__(320, 2)
k1_conv_attn(const float* __restrict__ x, const float* __restrict__ attn_b)
{
    extern __shared__ float sm[];
    float* wT   = sm + K1_WT;
    float* bias = sm + K1_BIAS;
    float* awT  = sm + K1_AWT;
    float* ab   = sm + K1_AB;
    float* xs   = sm + K1_XS;
    float* qkv  = sm + K1_QKV;

    const int tid = threadIdx.x;
    const int b0  = blockIdx.x * NB;

    // ---- cooperative coalesced loads ----
    {
        const float4* s1 = reinterpret_cast<const float4*>(g_wT);
        float4* d1 = reinterpret_cast<float4*>(wT);
        for (int idx = tid; idx < 2048; idx += 320) d1[idx] = s1[idx];
        const float4* s2 = reinterpret_cast<const float4*>(g_awT);
        float4* d2 = reinterpret_cast<float4*>(awT);
        for (int idx = tid; idx < 256; idx += 320) d2[idx] = s2[idx];
        const float4* s3 = reinterpret_cast<const float4*>(x + (size_t)b0 * 576);
        float4* d3 = reinterpret_cast<float4*>(xs);
        for (int idx = tid; idx < 576; idx += 320) d3[idx] = s3[idx];
        if (tid < 128) bias[tid] = g_bias[tid];
        if (tid < 32)  ab[tid]   = attn_b[tid];
    }
    __syncthreads();

    // ---- Phase A: conv. task = 8 output channels x 5 positions (one row) ----
    // 320 tasks = 16 ch-octets x (4 batch x 5 rows). Weight LDS amortized over
    // 5 positions; x reads broadcast within warp (lanes share pg pairs).
    {
        const int g   = tid & 15;          // channel octet
        const int pg  = tid >> 4;          // 0..19
        const int bb  = pg / 5;
        const int i   = pg - bb * 5;       // output row
        const int oc0 = g << 3;

        ull acc[4][5];
        {
            const ulonglong2* bp = reinterpret_cast<const ulonglong2*>(bias + oc0);
            ulonglong2 bA = bp[0], bB = bp[1];
            #pragma unroll
            for (int j = 0; j < 5; ++j) {
                acc[0][j] = bA.x; acc[1][j] = bA.y;
                acc[2][j] = bB.x; acc[3][j] = bB.y;
            }
        }
        const float* xb = xs + bb * 576 + i * 6;
        #pragma unroll
        for (int ic = 0; ic < 16; ++ic) {
            const float* xr = xb + ic * 36;
            float x0[6], x1[6];
            #pragma unroll
            for (int c = 0; c < 6; ++c) { x0[c] = xr[c]; x1[c] = xr[6 + c]; }
            const float* wbase = wT + (ic * 4) * 128 + oc0;
            #pragma unroll
            for (int kk = 0; kk < 4; ++kk) {
                const ulonglong2* wp = reinterpret_cast<const ulonglong2*>(wbase + kk * 128);
                ulonglong2 wA = wp[0], wB = wp[1];
                const int dj = kk & 1;
                #pragma unroll
                for (int j = 0; j < 5; ++j) {
                    float xv = (kk & 2) ? x1[j + dj] : x0[j + dj];
                    ull xx = pk2(xv, xv);
                    acc[0][j] = ffma2(xx, wA.x, acc[0][j]);
                    acc[1][j] = ffma2(xx, wA.y, acc[1][j]);
                    acc[2][j] = ffma2(xx, wB.x, acc[2][j]);
                    acc[3][j] = ffma2(xx, wB.y, acc[3][j]);
                }
            }
        }

        if (g < 4) {
            // conv_out path: relu now, straight to Y
            float* dst = g_Y + (size_t)(b0 + bb) * KFEAT + oc0 * 25 + i * 5;
            #pragma unroll
            for (int p = 0; p < 4; ++p)
                #pragma unroll
                for (int j = 0; j < 5; ++j) {
                    float lo, hi; upk2(acc[p][j], lo, hi);
                    dst[(2 * p) * 25 + j]     = fmaxf(lo, 0.f);
                    dst[(2 * p + 1) * 25 + j] = fmaxf(hi, 0.f);
                }
        } else {
            // qkv path (dkh^-0.5 == 1): stash in smem
            float* dst = qkv + (bb * 96 + (oc0 - 32)) * 25 + i * 5;
            #pragma unroll
            for (int p = 0; p < 4; ++p)
                #pragma unroll
                for (int j = 0; j < 5; ++j) {
                    float lo, hi; upk2(acc[p][j], lo, hi);
                    dst[(2 * p) * 25 + j]     = lo;
                    dst[(2 * p + 1) * 25 + j] = hi;
                }
        }
    }
    __syncthreads();

    // ---- Phase B: attention. dkh=1 => logits[i][j] = q_i*k_j; ex2-domain ----
    {
        const int lane = tid & 31;
        const int wid  = tid >> 5;
        #pragma unroll 1
        for (int it = 0; it < 13; ++it) {
            int u = wid + it * 10;                 // (bb, head)
            if (u < 128 && lane < 25) {
                int bb = u >> 5, n = u & 31;
                float* qrow = qkv + (bb * 96 + n) * 25;
                const float* krow = qrow + 800;
                const float* vrow = qrow + 1600;
                float qi = qrow[lane] * 1.4426950408889634f;   // fold log2e
                float m = -1e30f;
                #pragma unroll
                for (int jj = 0; jj < 25; ++jj) m = fmaxf(m, qi * krow[jj]);
                float s = 0.f, a = 0.f;
                #pragma unroll
                for (int jj = 0; jj < 25; ++jj) {
                    float e = ex2f(fmaf(qi, krow[jj], -m));
                    s += e;
                    a = fmaf(e, vrow[jj], a);
                }
                qrow[lane] = a / s;    // overwrite dead q slot with attn out
            }
        }
    }
    __syncthreads();

    // ---- Phase C: 1x1 conv over attn channels (f32x2 over oc-pairs) ----
    {
        const int lane = tid & 31;
        const int wid  = tid >> 5;
        #pragma unroll 1
        for (int it = 0; it < 7; ++it) {
            int u = wid + it * 10;                 // (bb, oc-pair)
            if (u < 64 && lane < 25) {
                int bb = u >> 4, oc0 = (u & 15) * 2;
                const float* arow = qkv + bb * 2400;
                ull acc2 = *reinterpret_cast<const ull*>(ab + oc0);
                #pragma unroll
                for (int ic = 0; ic < 32; ++ic) {
                    float h = arow[ic * 25 + lane];
                    ull wp = *reinterpret_cast<const ull*>(awT + ic * 32 + oc0);
                    acc2 = ffma2(pk2(h, h), wp, acc2);
                }
                float lo, hi; upk2(acc2, lo, hi);
                float* dst = g_Y + (size_t)(b0 + bb) * KFEAT + (32 + oc0) * 25 + lane;
                dst[0]  = fmaxf(lo, 0.f);
                dst[25] = fmaxf(hi, 0.f);
            }
        }
    }
}

// ---------------------------------------------------------------------------
// Kernel 2: fc1 (64x128x1600 SGEMM per block) + fc2 (row-pair f32x2) + fc3
//   grid = 128 blocks, 256 threads, dyn smem 111648 B
// ---------------------------------------------------------------------------
#define K2_AS   0                      // 32 x 68  (As[k][row], pad 4)
#define K2_BS   2176                   // 32 x 128 (Bs[k][col])
#define K2_W2T  6272                   // 128 x 68 (w2T[k][o], pad 4)
#define K2_H1   14976                  // 64 x 129
#define K2_H2   23232                  // 64 x 65
#define K2_B1   27392                  // 128
#define K2_B2   27520                  // 64
#define K2_W3   27584                  // 320
#define K2_B3   27904                  // 8
#define K2_TOT  27912                  // 111648 B

extern "C" __global__ void __launch_bounds__(256)
k2_mlp(const float* __restrict__ w1, const float* __restrict__ b1,
       const float* __restrict__ w2, const float* __restrict__ b2,
       const float* __restrict__ w3, const float* __restrict__ b3,
       float* __restrict__ out)
{
    extern __shared__ float sm[];
    float* As  = sm + K2_AS;
    float* Bs  = sm + K2_BS;
    float* w2T = sm + K2_W2T;
    float* H1s = sm + K2_H1;
    float* H2s = sm + K2_H2;
    float* b1s = sm + K2_B1;
    float* b2s = sm + K2_B2;
    float* w3s = sm + K2_W3;
    float* b3s = sm + K2_B3;

    const int tid = threadIdx.x;
    const int rowBase = blockIdx.x * 64;

    // ---- preload small weights; w2 transposed [k][o] (pad 68) ----
    for (int idx = tid; idx < 8192; idx += 256) {
        int o = idx >> 7, k = idx & 127;
        w2T[k * 68 + o] = w2[idx];
    }
    for (int idx = tid; idx < 320; idx += 256) w3s[idx] = w3[idx];
    if (tid < 128) b1s[tid] = b1[tid];
    if (tid < 64)  b2s[tid] = b2[tid];
    if (tid < 8)   b3s[tid] = (tid < 5) ? b3[tid] : 0.f;

    // ---- fc1: C[64x128] = Y[64x1600] @ w1^T, 4x8 microtile, f32x2 ----
    const int r0 = (tid >> 4) * 4;     // 16 row groups
    const int c0 = (tid & 15) * 8;     // 16 col groups

    ull acc[4][4];
    #pragma unroll
    for (int i = 0; i < 4; ++i)
        #pragma unroll
        for (int p = 0; p < 4; ++p) acc[i][p] = 0ull;

    // staging: A rows bank-distinct (row = tid&63), B cols bank-distinct
    const int aRow = tid & 63;
    const int aKq  = tid >> 6;                       // 0..3 -> 8 k's each
    const int bN   = tid & 127;
    const int bKq  = tid >> 7;                       // 0..1 -> 16 k's each
    const float* Ysrc = g_Y + (size_t)(rowBase + aRow) * KFEAT + aKq * 8;
    const float* Bsrc = w1 + (size_t)bN * KFEAT + bKq * 16;

    float4 aP0, aP1, bP0, bP1, bP2, bP3;
    aP0 = *reinterpret_cast<const float4*>(Ysrc);
    aP1 = *reinterpret_cast<const float4*>(Ysrc + 4);
    bP0 = *reinterpret_cast<const float4*>(Bsrc);
    bP1 = *reinterpret_cast<const float4*>(Bsrc + 4);
    bP2 = *reinterpret_cast<const float4*>(Bsrc + 8);
    bP3 = *reinterpret_cast<const float4*>(Bsrc + 12);

    #pragma unroll 1
    for (int cc = 0; cc < 50; ++cc) {
        __syncthreads();
        {   // As[k][row], stride 68: conflict-free (lanes vary row)
            int kb = aKq * 8;
            As[(kb + 0) * 68 + aRow] = aP0.x;
            As[(kb + 1) * 68 + aRow] = aP0.y;
            As[(kb + 2) * 68 + aRow] = aP0.z;
            As[(kb + 3) * 68 + aRow] = aP0.w;
            As[(kb + 4) * 68 + aRow] = aP1.x;
            As[(kb + 5) * 68 + aRow] = aP1.y;
            As[(kb + 6) * 68 + aRow] = aP1.z;
            As[(kb + 7) * 68 + aRow] = aP1.w;
        }
        {   // Bs[k][n], stride 128: conflict-free (lanes vary n)
            int kb = bKq * 16;
            Bs[(kb + 0)  * 128 + bN] = bP0.x;
            Bs[(kb + 1)  * 128 + bN] = bP0.y;
            Bs[(kb + 2)  * 128 + bN] = bP0.z;
            Bs[(kb + 3)  * 128 + bN] = bP0.w;
            Bs[(kb + 4)  * 128 + bN] = bP1.x;
            Bs[(kb + 5)  * 128 + bN] = bP1.y;
            Bs[(kb + 6)  * 128 + bN] = bP1.z;
            Bs[(kb + 7)  * 128 + bN] = bP1.w;
            Bs[(kb + 8)  * 128 + bN] = bP2.x;
            Bs[(kb + 9)  * 128 + bN] = bP2.y;
            Bs[(kb + 10) * 128 + bN] = bP2.z;
            Bs[(kb + 11) * 128 + bN] = bP2.w;
            Bs[(kb + 12) * 128 + bN] = bP3.x;
            Bs[(kb + 13) * 128 + bN] = bP3.y;
            Bs[(kb + 14) * 128 + bN] = bP3.z;
            Bs[(kb + 15) * 128 + bN] = bP3.w;
        }
        __syncthreads();

        if (cc < 49) {   // register-prefetch next chunk (hidden under compute)
            const float* ys = Ysrc + (cc + 1) * 32;
            const float* bs = Bsrc + (cc + 1) * 32;
            aP0 = *reinterpret_cast<const float4*>(ys);
            aP1 = *reinterpret_cast<const float4*>(ys + 4);
            bP0 = *reinterpret_cast<const float4*>(bs);
            bP1 = *reinterpret_cast<const float4*>(bs + 4);
            bP2 = *reinterpret_cast<const float4*>(bs + 8);
            bP3 = *reinterpret_cast<const float4*>(bs + 12);
        }

        #pragma unroll 8
        for (int k = 0; k < 32; ++k) {
            float4 a4 = *reinterpret_cast<const float4*>(As + k * 68 + r0);
            const ulonglong2* bp = reinterpret_cast<const ulonglong2*>(Bs + k * 128 + c0);
            ulonglong2 bA = bp[0], bB = bp[1];
            ull ax;
            ax = pk2(a4.x, a4.x);
            acc[0][0] = ffma2(ax, bA.x, acc[0][0]);
            acc[0][1] = ffma2(ax, bA.y, acc[0][1]);
            acc[0][2] = ffma2(ax, bB.x, acc[0][2]);
            acc[0][3] = ffma2(ax, bB.y, acc[0][3]);
            ax = pk2(a4.y, a4.y);
            acc[1][0] = ffma2(ax, bA.x, acc[1][0]);
            acc[1][1] = ffma2(ax, bA.y, acc[1][1]);
            acc[1][2] = ffma2(ax, bB.x, acc[1][2]);
            acc[1][3] = ffma2(ax, bB.y, acc[1][3]);
            ax = pk2(a4.z, a4.z);
            acc[2][0] = ffma2(ax, bA.x, acc[2][0]);
            acc[2][1] = ffma2(ax, bA.y, acc[2][1]);
            acc[2][2] = ffma2(ax, bB.x, acc[2][2]);
            acc[2][3] = ffma2(ax, bB.y, acc[2][3]);
            ax = pk2(a4.w, a4.w);
            acc[3][0] = ffma2(ax, bA.x, acc[3][0]);
            acc[3][1] = ffma2(ax, bA.y, acc[3][1]);
            acc[3][2] = ffma2(ax, bB.x, acc[3][2]);
            acc[3][3] = ffma2(ax, bB.y, acc[3][3]);
        }
    }

    // ---- epilogue: +b1, relu -> H1s ----
    #pragma unroll
    for (int i = 0; i < 4; ++i)
        #pragma unroll
        for (int p = 0; p < 4; ++p) {
            float lo, hi; upk2(acc[i][p], lo, hi);
            H1s[(r0 + i) * 129 + c0 + 2 * p]     = fmaxf(lo + b1s[c0 + 2 * p],     0.f);
            H1s[(r0 + i) * 129 + c0 + 2 * p + 1] = fmaxf(hi + b1s[c0 + 2 * p + 1], 0.f);
        }
    __syncthreads();

    // ---- fc2: row-pairs packed in f32x2, 8 outs per thread, relu ----
    {
        const int rp = tid >> 3;               // row pair 0..31
        const int o0 = (tid & 7) * 8;          // out group
        ull a2c[8];
        #pragma unroll
        for (int oo = 0; oo < 8; ++oo) a2c[oo] = pk2(b2s[o0 + oo], b2s[o0 + oo]);
        const float* h0p = H1s + (2 * rp) * 129;
        const float* h1p = h0p + 129;
        #pragma unroll 4
        for (int k = 0; k < 128; ++k) {
            ull hh = pk2(h0p[k], h1p[k]);
            float4 w40 = *reinterpret_cast<const float4*>(w2T + k * 68 + o0);
            float4 w41 = *reinterpret_cast<const float4*>(w2T + k * 68 + o0 + 4);
            a2c[0] = ffma2(hh, pk2(w40.x, w40.x), a2c[0]);
            a2c[1] = ffma2(hh, pk2(w40.y, w40.y), a2c[1]);
            a2c[2] = ffma2(hh, pk2(w40.z, w40.z), a2c[2]);
            a2c[3] = ffma2(hh, pk2(w40.w, w40.w), a2c[3]);
            a2c[4] = ffma2(hh, pk2(w41.x, w41.x), a2c[4]);
            a2c[5] = ffma2(hh, pk2(w41.y, w41.y), a2c[5]);
            a2c[6] = ffma2(hh, pk2(w41.z, w41.z), a2c[6]);
            a2c[7] = ffma2(hh, pk2(w41.w, w41.w), a2c[7]);
        }
        #pragma unroll
        for (int oo = 0; oo < 8; ++oo) {
            float lo, hi; upk2(a2c[oo], lo, hi);
            H2s[(2 * rp) * 65 + o0 + oo]     = fmaxf(lo, 0.f);
            H2s[(2 * rp + 1) * 65 + o0 + oo] = fmaxf(hi, 0.f);
        }
    }
    __syncthreads();

    // ---- fc3: 64 rows x 5 outs, K=64 ----
    if (tid < 64) {
        const int row = tid;
        const float* h = H2s + row * 65;
        float a0 = b3s[0], a1 = b3s[1], a2 = b3s[2], a3 = b3s[3], a4 = b3s[4];
        #pragma unroll
        for (int k = 0; k < 64; ++k) {
            float hv = h[k];
            a0 = fmaf(hv, w3s[0 * 64 + k], a0);
            a1 = fmaf(hv, w3s[1 * 64 + k], a1);
            a2 = fmaf(hv, w3s[2 * 64 + k], a2);
            a3 = fmaf(hv, w3s[3 * 64 + k], a3);
            a4 = fmaf(hv, w3s[4 * 64 + k], a4);
        }
        float* dst = out + (size_t)(rowBase + row) * OUTC;
        dst[0] = a0; dst[1] = a1; dst[2] = a2; dst[3] = a3; dst[4] = a4;
    }
}

// ---------------------------------------------------------------------------
// Launch (graph-capturable: kernel launches only, default stream)
// ---------------------------------------------------------------------------
extern "C" void kernel_launch(void* const* d_in, const int* in_sizes, int n_in,
                              void* d_out, int out_size)
{
    const float* x      = (const float*)d_in[0];
    const float* conv_w = (const float*)d_in[1];
    const float* conv_b = (const float*)d_in[2];
    const float* qkv_w  = (const float*)d_in[3];
    const float* qkv_b  = (const float*)d_in[4];
    const float* attn_w = (const float*)d_in[5];
    const float* attn_b = (const float*)d_in[6];
    const float* w1     = (const float*)d_in[7];
    const float* b1     = (const float*)d_in[8];
    const float* w2     = (const float*)d_in[9];
    const float* b2     = (const float*)d_in[10];
    const float* w3     = (const float*)d_in[11];
    const float* b3     = (const float*)d_in[12];
    float* out = (float*)d_out;

    const int SM1 = K1_TOT * (int)sizeof(float);   // 85120 B
    const int SM2 = K2_TOT * (int)sizeof(float);   // 111648 B
    cudaFuncSetAttribute(k1_conv_attn, cudaFuncAttributeMaxDynamicSharedMemorySize, SM1);
    cudaFuncSetAttribute(k2_mlp,       cudaFuncAttributeMaxDynamicSharedMemorySize, SM2);

    k0_prep<<<4, 256>>>(conv_w, conv_b, qkv_w, qkv_b, attn_w);
    k1_conv_attn<<<B_TOT / NB, 320, SM1>>>(x, attn_b);
    k2_mlp<<<B_TOT / 64, 256, SM2>>>(w1, b1, w2, b2, w3, b3, out);
}